// round 5
// baseline (speedup 1.0000x reference)
#include <cuda_runtime.h>

#define TT 100   // sequence length
#define CC 16    // input embedding dim
#define HH 64    // head size
#define DD 256   // dense dim
#define RS 20    // padded row stride: float4-aligned, conflict-free LDS.128 column walk

// wei gets 4 zero pad rows (rows 100..103) so the paired-quad z tile needs no branch
#define WEI_ROWS 104

typedef unsigned long long ull;

// ---- packed fp32x2 helpers (sm_100+ PTX; .rn rounding = bit-identical to FFMA) ----
__device__ __forceinline__ ull ffma2(ull a, ull b, ull acc) {
    ull d;
    asm("fma.rn.f32x2 %0, %1, %2, %3;" : "=l"(d) : "l"(a), "l"(b), "l"(acc));
    return d;
}
__device__ __forceinline__ ull pack2(float lo, float hi) {
    ull r;
    asm("mov.b64 %0, {%1, %2};" : "=l"(r) : "f"(lo), "f"(hi));
    return r;
}
__device__ __forceinline__ float hadd2(ull v) {
    float lo, hi;
    asm("mov.b64 {%0, %1}, %2;" : "=f"(lo), "=f"(hi) : "l"(v));
    return lo + hi;
}

// ---- MUFU-free expf (args <= 0). Magic-number rint + deg-5 poly for 2^f.
// exp(x) = 2^(x*log2e); r = rint(t) extracted from the magic-add float's low
// mantissa bits; (bits(y)<<23) == (int)r<<23 exactly (mod 2^32). Max rel err
// ~2.4e-6 over f in [-0.5,0.5]. No MUFU, no F2I — pure FMA/ALU pipe.
__device__ __forceinline__ float fast_exp(float x) {
    const float L2E   = 1.4426950408889634f;
    const float MAGIC = 12582912.0f;          // 1.5 * 2^23
    x = fmaxf(x, -80.0f);                     // keep 2^r in normal range
    float y = fmaf(x, L2E, MAGIC);            // rint(x*L2E) + MAGIC
    float f = fmaf(x, L2E, MAGIC - y);        // frac in [-0.5, 0.5]
    float p = 1.3333558146428443e-3f;         // ln2^5/120
    p = fmaf(p, f, 9.6181291076284771e-3f);   // ln2^4/24
    p = fmaf(p, f, 5.5504108664821579e-2f);   // ln2^3/6
    p = fmaf(p, f, 2.4022650695910071e-1f);   // ln2^2/2
    p = fmaf(p, f, 6.9314718055994531e-1f);   // ln2
    p = fmaf(p, f, 1.0f);
    return __int_as_float(__float_as_int(p) + (__float_as_int(y) << 23));
}

// Folded weights (computed by prologue kernels each call — deterministic)
__device__ float g_Wqc[CC * DD];
__device__ float g_Wkc[CC * DD];
__device__ float g_Wvc[CC * DD];
__device__ float g_M[CC * CC];

// ---------------------------------------------------------------------------
// Prologue 1: fold chained projections. Wo[16,256] = W1[16,64] @ W2[64,256]
// ---------------------------------------------------------------------------
__global__ void combine_kernel(const float* __restrict__ Wk, const float* __restrict__ Wq,
                               const float* __restrict__ Wv, const float* __restrict__ Wdk,
                               const float* __restrict__ Wdq, const float* __restrict__ Wdv) {
    __shared__ float w1s[CC * HH];
    const float* W1;
    const float* W2;
    float* Wo;
    if (blockIdx.x == 0)      { W1 = Wq; W2 = Wdq; Wo = g_Wqc; }
    else if (blockIdx.x == 1) { W1 = Wk; W2 = Wdk; Wo = g_Wkc; }
    else                      { W1 = Wv; W2 = Wdv; Wo = g_Wvc; }

    int tid = threadIdx.x;
    for (int i = tid; i < CC * HH; i += 256) w1s[i] = W1[i];
    __syncthreads();

    int d = tid;  // one output column
    float w2r[HH];
#pragma unroll
    for (int h = 0; h < HH; h++) w2r[h] = W2[h * DD + d];  // all 64 loads in flight

#pragma unroll
    for (int c = 0; c < CC; c++) {
        float acc = 0.f;
#pragma unroll
        for (int h = 0; h < HH; h++) acc += w1s[c * HH + h] * w2r[h];
        Wo[c * DD + d] = acc;
    }
}

// ---------------------------------------------------------------------------
// Prologue 2: M[16,16] = 0.25 * Wqc @ Wkc^T   (0.25 = C^-0.5, C=16)
// ---------------------------------------------------------------------------
__global__ void m_kernel() {
    int i = threadIdx.x;
    int c  = i >> 4;
    int c2 = i & 15;
    float s = 0.f;
#pragma unroll 8
    for (int d = 0; d < DD; d += 4) {
        float4 a = *reinterpret_cast<const float4*>(&g_Wqc[c * DD + d]);
        float4 b = *reinterpret_cast<const float4*>(&g_Wkc[c2 * DD + d]);
        s += a.x * b.x + a.y * b.y + a.z * b.z + a.w * b.w;
    }
    g_M[c * CC + c2] = s * 0.25f;
}

// ---------------------------------------------------------------------------
// Main fused kernel: one CTA per batch element.
// ---------------------------------------------------------------------------
__global__ void __launch_bounds__(256, 2)
head_kernel(const float* __restrict__ x, float* __restrict__ out, int B) {
    extern __shared__ float sm[];
    float* xs  = sm;                               // TT*RS = 2000
    float* yz  = sm + TT * RS;                     // TT*RS = 2000
    float* wei = sm + 2 * TT * RS;                 // WEI_ROWS*TT = 10400
    float* Ms  = sm + 2 * TT * RS + WEI_ROWS * TT; // 256

    const int tid  = threadIdx.x;
    const int warp = tid >> 5;
    const int lane = tid & 31;
    const long long b = blockIdx.x;
    const float* xb = x + b * (long long)(TT * CC);

    for (int i = tid; i < TT * CC; i += 256)
        xs[(i >> 4) * RS + (i & 15)] = xb[i];
    if (tid < CC * CC) Ms[tid] = g_M[tid];
    for (int i = tid; i < (WEI_ROWS - TT) * TT; i += 256)
        wei[TT * TT + i] = 0.f;
    __syncthreads();

    // ---- y = x @ M ----
    for (int i = tid; i < TT * CC; i += 256) {
        int t = i >> 4, j = i & 15;
        float a = 0.f;
#pragma unroll
        for (int c = 0; c < CC; c++) a += xs[t * RS + c] * Ms[c * CC + j];
        yz[t * RS + j] = a;
    }
    __syncthreads();

    // ---- logits: wei[t][s] = y[t]·x[s] (causal; zero above diagonal) ----
    for (int g = warp; g < 25; g += 8) {
        int t0 = g * 4;
        ulonglong2 yr[4][4];
#pragma unroll
        for (int j = 0; j < 4; j++)
#pragma unroll
            for (int q = 0; q < 4; q++)
                yr[j][q] = *reinterpret_cast<const ulonglong2*>(&yz[(t0 + j) * RS + q * 4]);

        for (int s = lane; s < TT; s += 32) {
            ull a[4] = {0ull, 0ull, 0ull, 0ull};
            if (s <= t0 + 3) {
#pragma unroll
                for (int q = 0; q < 4; q++) {
                    ulonglong2 xv = *reinterpret_cast<const ulonglong2*>(&xs[s * RS + q * 4]);
#pragma unroll
                    for (int j = 0; j < 4; j++) {
                        a[j] = ffma2(yr[j][q].x, xv.x, a[j]);
                        a[j] = ffma2(yr[j][q].y, xv.y, a[j]);
                    }
                }
            }
#pragma unroll
            for (int j = 0; j < 4; j++)
                wei[(t0 + j) * TT + s] = (s <= t0 + j) ? hadd2(a[j]) : 0.f;
        }
    }
    __syncthreads();

    // ---- causal softmax, one warp per row (exp is MUFU-free) ----
    for (int t = warp; t < TT; t += 8) {
        float m = -1e30f;
        for (int s = lane; s <= t; s += 32) m = fmaxf(m, wei[t * TT + s]);
#pragma unroll
        for (int o = 16; o; o >>= 1) m = fmaxf(m, __shfl_xor_sync(0xffffffffu, m, o));
        float sum = 0.f;
        for (int s = lane; s <= t; s += 32) {
            float e = fast_exp(wei[t * TT + s] - m);
            wei[t * TT + s] = e;
            sum += e;
        }
#pragma unroll
        for (int o = 16; o; o >>= 1) sum += __shfl_xor_sync(0xffffffffu, sum, o);
        float inv = 1.f / sum;
        for (int s = lane; s <= t; s += 32) wei[t * TT + s] *= inv;
    }
    __syncthreads();

    // ---- z = wei @ x  (overwrites yz) ----
    // Balanced: thread owns quad-row blocks qa=tb and qb=25-tb, so per-thread
    // s-work is ~constant (qa needs 4tb+4 s's, qb needs min(104-4tb,100)).
    // Quads 25 (rows 100-103) are zeroed pad rows; stores guarded by t<TT.
    if (tid < 208) {  // 13 tb * 16 columns
        int c  = tid & 15;
        int tb = tid >> 4;          // 0..12
        int qa = tb;                // rows 4qa..4qa+3
        int qb = 25 - tb;           // rows 4qb..4qb+3
        int sa = 4 * qa + 4;        // s-count for quad A (multiple of 4)
        int sb = min(4 * qb + 4, TT);  // s-count for quad B (multiple of 4)
        ull a[8];
#pragma unroll
        for (int j = 0; j < 8; j++) a[j] = 0ull;
        for (int s0 = 0; s0 < sb; s0 += 4) {
            ull xp0 = pack2(xs[(s0 + 0) * RS + c], xs[(s0 + 1) * RS + c]);
            ull xp1 = pack2(xs[(s0 + 2) * RS + c], xs[(s0 + 3) * RS + c]);
            if (s0 < sa) {
#pragma unroll
                for (int j = 0; j < 4; j++) {
                    ulonglong2 w4 = *reinterpret_cast<const ulonglong2*>(&wei[(4 * qa + j) * TT + s0]);
                    a[j] = ffma2(w4.x, xp0, a[j]);
                    a[j] = ffma2(w4.y, xp1, a[j]);
                }
            }
#pragma unroll
            for (int j = 0; j < 4; j++) {
                ulonglong2 w4 = *reinterpret_cast<const ulonglong2*>(&wei[(4 * qb + j) * TT + s0]);
                a[4 + j] = ffma2(w4.x, xp0, a[4 + j]);
                a[4 + j] = ffma2(w4.y, xp1, a[4 + j]);
            }
        }
#pragma unroll
        for (int j = 0; j < 4; j++)
            yz[(4 * qa + j) * RS + c] = hadd2(a[j]);
#pragma unroll
        for (int j = 0; j < 4; j++) {
            int t = 4 * qb + j;
            if (t < TT) yz[t * RS + c] = hadd2(a[4 + j]);
        }
    }
    __syncthreads();

    // ---- out = z @ Wvc ----
    {
        int d4 = tid & 63;   // column group 0..63
        int tc = tid >> 6;   // t-chunk 0..3 -> 25 rows each
        ull wp[8][4];
#pragma unroll
        for (int c2 = 0; c2 < 8; c2++) {
            float4 w0 = *reinterpret_cast<const float4*>(&g_Wvc[(2 * c2 + 0) * DD + d4 * 4]);
            float4 w1 = *reinterpret_cast<const float4*>(&g_Wvc[(2 * c2 + 1) * DD + d4 * 4]);
            wp[c2][0] = pack2(w0.x, w1.x);
            wp[c2][1] = pack2(w0.y, w1.y);
            wp[c2][2] = pack2(w0.z, w1.z);
            wp[c2][3] = pack2(w0.w, w1.w);
        }

        float* ob = out + b * (long long)(TT * DD);
        for (int t = tc * 25; t < tc * 25 + 25; t++) {
            ull acc[4] = {0ull, 0ull, 0ull, 0ull};
#pragma unroll
            for (int q = 0; q < 4; q++) {
                ulonglong2 zp = *reinterpret_cast<const ulonglong2*>(&yz[t * RS + q * 4]);
#pragma unroll
                for (int j = 0; j < 4; j++) {
                    acc[j] = ffma2(zp.x, wp[2 * q + 0][j], acc[j]);
                    acc[j] = ffma2(zp.y, wp[2 * q + 1][j], acc[j]);
                }
            }
            float4 o4;
            o4.x = hadd2(acc[0]);
            o4.y = hadd2(acc[1]);
            o4.z = hadd2(acc[2]);
            o4.w = hadd2(acc[3]);
            *reinterpret_cast<float4*>(&ob[t * DD + d4 * 4]) = o4;
        }
    }
}

// ---------------------------------------------------------------------------
extern "C" void kernel_launch(void* const* d_in, const int* in_sizes, int n_in,
                              void* d_out, int out_size) {
    const float* x   = (const float*)d_in[0];
    const float* Wk  = (const float*)d_in[1];
    const float* Wq  = (const float*)d_in[2];
    const float* Wv  = (const float*)d_in[3];
    const float* Wdk = (const float*)d_in[4];
    const float* Wdq = (const float*)d_in[5];
    const float* Wdv = (const float*)d_in[6];
    float* out = (float*)d_out;

    int B = in_sizes[0] / (TT * CC);  // 4096

    const int smem_bytes = (2 * TT * RS + WEI_ROWS * TT + CC * CC) * (int)sizeof(float); // 58624
    cudaFuncSetAttribute(head_kernel, cudaFuncAttributeMaxDynamicSharedMemorySize, smem_bytes);

    combine_kernel<<<3, 256>>>(Wk, Wq, Wv, Wdk, Wdq, Wdv);
    m_kernel<<<1, 256>>>();
    head_kernel<<<B, 256, smem_bytes>>>(x, out, B);
}

// round 6
// speedup vs baseline: 1.3248x; 1.3248x over previous
#include <cuda_runtime.h>

#define TT 100   // sequence length
#define CC 16    // input embedding dim
#define HH 64    // head size
#define DD 256   // dense dim
#define RS 20    // padded row stride: float4-aligned, conflict-free LDS.128 column walk

// wei gets 4 zero pad rows (rows 100..103) so the paired-quad z tile needs no branch
#define WEI_ROWS 104

typedef unsigned long long ull;

// ---- packed fp32x2 helpers (sm_100+ PTX; .rn rounding = bit-identical to FFMA) ----
__device__ __forceinline__ ull ffma2(ull a, ull b, ull acc) {
    ull d;
    asm("fma.rn.f32x2 %0, %1, %2, %3;" : "=l"(d) : "l"(a), "l"(b), "l"(acc));
    return d;
}
__device__ __forceinline__ ull pack2(float lo, float hi) {
    ull r;
    asm("mov.b64 %0, {%1, %2};" : "=l"(r) : "f"(lo), "f"(hi));
    return r;
}
__device__ __forceinline__ float hadd2(ull v) {
    float lo, hi;
    asm("mov.b64 {%0, %1}, %2;" : "=f"(lo), "=f"(hi) : "l"(v));
    return lo + hi;
}

// ---- MUFU-free expf (args <= 0). Magic-number rint + deg-5 poly for 2^f. ----
__device__ __forceinline__ float fast_exp(float x) {
    const float L2E   = 1.4426950408889634f;
    const float MAGIC = 12582912.0f;          // 1.5 * 2^23
    x = fmaxf(x, -80.0f);
    float y = fmaf(x, L2E, MAGIC);
    float f = fmaf(x, L2E, MAGIC - y);
    float p = 1.3333558146428443e-3f;
    p = fmaf(p, f, 9.6181291076284771e-3f);
    p = fmaf(p, f, 5.5504108664821579e-2f);
    p = fmaf(p, f, 2.4022650695910071e-1f);
    p = fmaf(p, f, 6.9314718055994531e-1f);
    p = fmaf(p, f, 1.0f);
    return __int_as_float(__float_as_int(p) + (__float_as_int(y) << 23));
}

// Folded weights (computed by prologue kernels each call — deterministic)
__device__ float g_Wqc[CC * DD];
__device__ float g_Wkc[CC * DD];
__device__ float g_Wvc[CC * DD];
__device__ float g_M[CC * CC];

// ---------------------------------------------------------------------------
// Prologue 1: fold chained projections. Wo[16,256] = W1[16,64] @ W2[64,256]
// ---------------------------------------------------------------------------
__global__ void combine_kernel(const float* __restrict__ Wk, const float* __restrict__ Wq,
                               const float* __restrict__ Wv, const float* __restrict__ Wdk,
                               const float* __restrict__ Wdq, const float* __restrict__ Wdv) {
    __shared__ float w1s[CC * HH];
    const float* W1;
    const float* W2;
    float* Wo;
    if (blockIdx.x == 0)      { W1 = Wq; W2 = Wdq; Wo = g_Wqc; }
    else if (blockIdx.x == 1) { W1 = Wk; W2 = Wdk; Wo = g_Wkc; }
    else                      { W1 = Wv; W2 = Wdv; Wo = g_Wvc; }

    int tid = threadIdx.x;
    for (int i = tid; i < CC * HH; i += 256) w1s[i] = W1[i];
    __syncthreads();

    int d = tid;  // one output column
    float w2r[HH];
#pragma unroll
    for (int h = 0; h < HH; h++) w2r[h] = W2[h * DD + d];  // all 64 loads in flight

#pragma unroll
    for (int c = 0; c < CC; c++) {
        float a0 = 0.f, a1 = 0.f;  // ILP-2 chains
#pragma unroll
        for (int h = 0; h < HH; h += 2) {
            a0 += w1s[c * HH + h]     * w2r[h];
            a1 += w1s[c * HH + h + 1] * w2r[h + 1];
        }
        Wo[c * DD + d] = a0 + a1;
    }
}

// ---------------------------------------------------------------------------
// Prologue 2: M[16,16] = 0.25 * Wqc @ Wkc^T   (0.25 = C^-0.5, C=16)
// ---------------------------------------------------------------------------
__global__ void m_kernel() {
    int i = threadIdx.x;
    int c  = i >> 4;
    int c2 = i & 15;
    float s0 = 0.f, s1 = 0.f;
#pragma unroll 8
    for (int d = 0; d < DD; d += 8) {
        float4 a = *reinterpret_cast<const float4*>(&g_Wqc[c * DD + d]);
        float4 b = *reinterpret_cast<const float4*>(&g_Wkc[c2 * DD + d]);
        s0 += a.x * b.x + a.y * b.y + a.z * b.z + a.w * b.w;
        float4 a2 = *reinterpret_cast<const float4*>(&g_Wqc[c * DD + d + 4]);
        float4 b2 = *reinterpret_cast<const float4*>(&g_Wkc[c2 * DD + d + 4]);
        s1 += a2.x * b2.x + a2.y * b2.y + a2.z * b2.z + a2.w * b2.w;
    }
    g_M[c * CC + c2] = (s0 + s1) * 0.25f;
}

// ---------------------------------------------------------------------------
// Main fused kernel: one CTA per batch element, occupancy 3.
//   y = x@M ; wei = softmax(tril(y@x^T)) fused in-register; z = wei@x;
//   out = z@Wvc
// ---------------------------------------------------------------------------
__global__ void __launch_bounds__(256, 3)
head_kernel(const float* __restrict__ x, float* __restrict__ out, int B) {
    extern __shared__ float sm[];
    float* xs  = sm;                               // TT*RS = 2000
    float* yz  = sm + TT * RS;                     // TT*RS = 2000
    float* wei = sm + 2 * TT * RS;                 // WEI_ROWS*TT = 10400
    float* Ms  = sm + 2 * TT * RS + WEI_ROWS * TT; // 256

    const int tid  = threadIdx.x;
    const int warp = tid >> 5;
    const int lane = tid & 31;
    const long long b = blockIdx.x;
    const float* xb = x + b * (long long)(TT * CC);

    // Load x tile + M; zero ALL of wei (upper triangle is never stored later)
    for (int i = tid; i < TT * CC; i += 256)
        xs[(i >> 4) * RS + (i & 15)] = xb[i];
    if (tid < CC * CC) Ms[tid] = g_M[tid];
    {
        float4 z4 = make_float4(0.f, 0.f, 0.f, 0.f);
        for (int i = tid; i < (WEI_ROWS * TT) / 4; i += 256)
            reinterpret_cast<float4*>(wei)[i] = z4;
    }
    __syncthreads();

    // ---- y = x @ M ----
    for (int i = tid; i < TT * CC; i += 256) {
        int t = i >> 4, j = i & 15;
        float a = 0.f;
#pragma unroll
        for (int c = 0; c < CC; c++) a += xs[t * RS + c] * Ms[c * CC + j];
        yz[t * RS + j] = a;
    }
    __syncthreads();

    // ---- logits + softmax FUSED: warp owns 2 rows (t0, t0+1) per block ----
    // Logits stay in registers; max/exp/sum via shfl butterflies; single store
    // of final probabilities. Upper triangle remains the pre-zeroed 0.
    for (int g = warp; g < 50; g += 8) {
        int t0 = 2 * g;
        ulonglong2 yr0[4], yr1[4];
#pragma unroll
        for (int q = 0; q < 4; q++) {
            yr0[q] = *reinterpret_cast<const ulonglong2*>(&yz[(t0 + 0) * RS + q * 4]);
            yr1[q] = *reinterpret_cast<const ulonglong2*>(&yz[(t0 + 1) * RS + q * 4]);
        }

        float l0[4], l1[4];
        float m0 = -1e30f, m1 = -1e30f;
#pragma unroll
        for (int it = 0; it < 4; it++) {
            int s = lane + 32 * it;
            l0[it] = 0.f; l1[it] = 0.f;
            if (s <= t0 + 1) {
                ull A0 = 0ull, A1 = 0ull;
#pragma unroll
                for (int q = 0; q < 4; q++) {
                    ulonglong2 xv = *reinterpret_cast<const ulonglong2*>(&xs[s * RS + q * 4]);
                    A0 = ffma2(yr0[q].x, xv.x, A0);
                    A0 = ffma2(yr0[q].y, xv.y, A0);
                    A1 = ffma2(yr1[q].x, xv.x, A1);
                    A1 = ffma2(yr1[q].y, xv.y, A1);
                }
                l0[it] = hadd2(A0);
                l1[it] = hadd2(A1);
                m1 = fmaxf(m1, l1[it]);
                if (s <= t0) m0 = fmaxf(m0, l0[it]);
            }
        }
#pragma unroll
        for (int o = 16; o; o >>= 1) {
            m0 = fmaxf(m0, __shfl_xor_sync(0xffffffffu, m0, o));
            m1 = fmaxf(m1, __shfl_xor_sync(0xffffffffu, m1, o));
        }

        float sum0 = 0.f, sum1 = 0.f;
#pragma unroll
        for (int it = 0; it < 4; it++) {
            int s = lane + 32 * it;
            if (s <= t0 + 1) {
                float e1 = fast_exp(l1[it] - m1);
                l1[it] = e1;
                sum1 += e1;
                if (s <= t0) {
                    float e0 = fast_exp(l0[it] - m0);
                    l0[it] = e0;
                    sum0 += e0;
                }
            }
        }
#pragma unroll
        for (int o = 16; o; o >>= 1) {
            sum0 += __shfl_xor_sync(0xffffffffu, sum0, o);
            sum1 += __shfl_xor_sync(0xffffffffu, sum1, o);
        }
        float inv0 = 1.f / sum0;
        float inv1 = 1.f / sum1;
#pragma unroll
        for (int it = 0; it < 4; it++) {
            int s = lane + 32 * it;
            if (s <= t0 + 1) {
                wei[(t0 + 1) * TT + s] = l1[it] * inv1;
                if (s <= t0) wei[t0 * TT + s] = l0[it] * inv0;
            }
        }
    }
    __syncthreads();

    // ---- z = wei @ x  (overwrites yz) ----
    // Balanced paired quads (qa=tb, qb=25-tb); wei float4 rows give natural
    // packed s-pairs; pad rows 100-103 are zeroed.
    if (tid < 208) {  // 13 tb * 16 columns
        int c  = tid & 15;
        int tb = tid >> 4;          // 0..12
        int qa = tb;
        int qb = 25 - tb;
        int sa = 4 * qa + 4;
        int sb = min(4 * qb + 4, TT);
        ull a[8];
#pragma unroll
        for (int j = 0; j < 8; j++) a[j] = 0ull;
        for (int s0 = 0; s0 < sb; s0 += 4) {
            ull xp0 = pack2(xs[(s0 + 0) * RS + c], xs[(s0 + 1) * RS + c]);
            ull xp1 = pack2(xs[(s0 + 2) * RS + c], xs[(s0 + 3) * RS + c]);
            if (s0 < sa) {
#pragma unroll
                for (int j = 0; j < 4; j++) {
                    ulonglong2 w4 = *reinterpret_cast<const ulonglong2*>(&wei[(4 * qa + j) * TT + s0]);
                    a[j] = ffma2(w4.x, xp0, a[j]);
                    a[j] = ffma2(w4.y, xp1, a[j]);
                }
            }
#pragma unroll
            for (int j = 0; j < 4; j++) {
                ulonglong2 w4 = *reinterpret_cast<const ulonglong2*>(&wei[(4 * qb + j) * TT + s0]);
                a[4 + j] = ffma2(w4.x, xp0, a[4 + j]);
                a[4 + j] = ffma2(w4.y, xp1, a[4 + j]);
            }
        }
#pragma unroll
        for (int j = 0; j < 4; j++)
            yz[(4 * qa + j) * RS + c] = hadd2(a[j]);
#pragma unroll
        for (int j = 0; j < 4; j++) {
            int t = 4 * qb + j;
            if (t < TT) yz[t * RS + c] = hadd2(a[4 + j]);
        }
    }
    __syncthreads();

    // ---- out = z @ Wvc ----
    // Thread owns 2 output columns (wp = 32 regs, fits occ 3) and 50 t rows.
    {
        int d2 = tid & 127;  // column pair 0..127
        int tc = tid >> 7;   // row half 0..1
        ull wp[8][2];
#pragma unroll
        for (int c2 = 0; c2 < 8; c2++) {
            float2 w0 = *reinterpret_cast<const float2*>(&g_Wvc[(2 * c2 + 0) * DD + 2 * d2]);
            float2 w1 = *reinterpret_cast<const float2*>(&g_Wvc[(2 * c2 + 1) * DD + 2 * d2]);
            wp[c2][0] = pack2(w0.x, w1.x);
            wp[c2][1] = pack2(w0.y, w1.y);
        }

        float* ob = out + b * (long long)(TT * DD);
        for (int t = tc * 50; t < tc * 50 + 50; t++) {
            ull acc0 = 0ull, acc1 = 0ull;
#pragma unroll
            for (int q = 0; q < 4; q++) {
                ulonglong2 zp = *reinterpret_cast<const ulonglong2*>(&yz[t * RS + q * 4]);
                acc0 = ffma2(zp.x, wp[2 * q + 0][0], acc0);
                acc0 = ffma2(zp.y, wp[2 * q + 1][0], acc0);
                acc1 = ffma2(zp.x, wp[2 * q + 0][1], acc1);
                acc1 = ffma2(zp.y, wp[2 * q + 1][1], acc1);
            }
            float2 o2;
            o2.x = hadd2(acc0);
            o2.y = hadd2(acc1);
            *reinterpret_cast<float2*>(&ob[t * DD + 2 * d2]) = o2;
        }
    }
}

// ---------------------------------------------------------------------------
extern "C" void kernel_launch(void* const* d_in, const int* in_sizes, int n_in,
                              void* d_out, int out_size) {
    const float* x   = (const float*)d_in[0];
    const float* Wk  = (const float*)d_in[1];
    const float* Wq  = (const float*)d_in[2];
    const float* Wv  = (const float*)d_in[3];
    const float* Wdk = (const float*)d_in[4];
    const float* Wdq = (const float*)d_in[5];
    const float* Wdv = (const float*)d_in[6];
    float* out = (float*)d_out;

    int B = in_sizes[0] / (TT * CC);  // 4096

    const int smem_bytes = (2 * TT * RS + WEI_ROWS * TT + CC * CC) * (int)sizeof(float); // 58624
    cudaFuncSetAttribute(head_kernel, cudaFuncAttributeMaxDynamicSharedMemorySize, smem_bytes);

    combine_kernel<<<3, 256>>>(Wk, Wq, Wv, Wdk, Wdq, Wdv);
    m_kernel<<<1, 256>>>();
    head_kernel<<<B, 256, smem_bytes>>>(x, out, B);
}